// round 15
// baseline (speedup 1.0000x reference)
#include <cuda_runtime.h>
#include <cstdint>

// ---------------------------------------------------------------------------
// Sequential LSTM rollout, N=10000 steps, H=1024.
// EXACT R7 kernel (best: 18.6ms) + ONE change: staggered 4-lane polling.
// Lanes 0-3 of warp 0 poll g_cnt in divergent loops, phase-offset ~130cyc via
// %clock spin -> counter sampled every ~130cyc instead of once per ~500cyc L2
// round trip. Winner writes the smem relay (st.release.cta); other pollers
// exit via ld.acquire.cta on the relay word. Ordering chain identical to R7
// (fence+RED -> acquire.gpu -> release.cta -> acquire.cta), winner may be any
// of lanes 0-3. Everything else byte-identical to R7.
// CTA b owns h[8b..8b+8) and gate rows {g*1024 + 8b + j}.
// Warp w owns k in [128w,128w+128).
// ---------------------------------------------------------------------------

#define HDIM  1024
#define NCTA  128
#define TPB   256
#define NWARP 8
#define WPT   64           // f32x2 weight pairs per thread (=128 k floats)

typedef unsigned long long ull;

__device__ __align__(16) float g_hbuf[2][HDIM];
__device__ unsigned            g_cnt;

__device__ __forceinline__ ull ffma2(ull a, ull b, ull c) {
    ull d;
    asm("fma.rn.f32x2 %0, %1, %2, %3;" : "=l"(d) : "l"(a), "l"(b), "l"(c));
    return d;
}
__device__ __forceinline__ ull fadd2(ull a, ull b) {
    ull d;
    asm("add.rn.f32x2 %0, %1, %2;" : "=l"(d) : "l"(a), "l"(b));
    return d;
}
__device__ __forceinline__ float pairsum(ull a) {
    float lo = __uint_as_float((unsigned)(a & 0xffffffffull));
    float hi = __uint_as_float((unsigned)(a >> 32));
    return lo + hi;
}
__device__ __forceinline__ float sigf(float x) {
    return 1.0f / (1.0f + __expf(-x));
}
__device__ __forceinline__ unsigned ld_acq_gpu(const unsigned* p) {
    unsigned v;
    asm volatile("ld.acquire.gpu.u32 %0, [%1];" : "=r"(v) : "l"(p));
    return v;
}
__device__ __forceinline__ uint32_t smem_u32(const void* p) {
    uint32_t a;
    asm("{ .reg .u64 t; cvta.to.shared.u64 t, %1; cvt.u32.u64 %0, t; }"
        : "=r"(a) : "l"(p));
    return a;
}
__device__ __forceinline__ unsigned clk32() {
    unsigned c;
    asm volatile("mov.u32 %0, %%clock;" : "=r"(c));
    return c;
}

__global__ void lstm_init_kernel() {
    if (threadIdx.x == 0) g_cnt = 0u;
}

__global__ void __launch_bounds__(TPB) lstm_kernel(
    const float* __restrict__ x,      // [1024]
    const float* __restrict__ W_ih,   // [4096,1024] row-major
    const float* __restrict__ W_hh,   // [4096,1024] row-major
    const float* __restrict__ b_ih,   // [4096]
    const float* __restrict__ b_hh,   // [4096]
    float* __restrict__ out,          // [N,1024]
    int N)
{
    __shared__ float    sh_h[HDIM];        // warp w owns [128w,128w+128): private
    __shared__ float    sh_part[2][TPB];   // parity-double-buffered partials
    __shared__ unsigned sh_step;           // monotonic step relay

    const int tid = threadIdx.x;
    const int w   = tid >> 5;
    const int l   = tid & 31;
    const int cta = blockIdx.x;
    const int gt  = l >> 3;                // gate 0..3 (i,f,g,o)
    const int jj  = l & 7;                 // local h index 0..7
    const int rowG = gt * HDIM + cta * 8 + jj;
    const uint32_t stepAddr = smem_u32(&sh_step);

    if (tid == 0) sh_step = 0u;

    // ---- stage x into shared (reuse sh_h) ----
    ((float4*)sh_h)[tid] = ((const float4*)x)[tid];
    __syncthreads();

    // ---- prologue: x_gates = x @ W_ih^T + b_ih + b_hh for this CTA's rows ----
    float xg = 0.f;
    {
        const ull* wp = (const ull*)W_ih + (size_t)rowG * (HDIM / 2) + w * WPT;
        const ull* hp = (const ull*)sh_h + w * WPT;
        ull a0 = 0, a1 = 0, a2 = 0, a3 = 0;
        #pragma unroll
        for (int i = 0; i < WPT; i += 4) {
            a0 = ffma2(wp[i + 0], hp[i + 0], a0);
            a1 = ffma2(wp[i + 1], hp[i + 1], a1);
            a2 = ffma2(wp[i + 2], hp[i + 2], a2);
            a3 = ffma2(wp[i + 3], hp[i + 3], a3);
        }
        a0 = fadd2(a0, a1); a2 = fadd2(a2, a3); a0 = fadd2(a0, a2);
        sh_part[0][w * 32 + l] = pairsum(a0);
        __syncthreads();
        if (w == 0) {
            float s = 0.f;
            #pragma unroll
            for (int ww = 0; ww < NWARP; ww++) s += sh_part[0][ww * 32 + l];
            xg = s + b_ih[rowG] + b_hh[rowG];
        }
        __syncthreads();
    }

    // ---- preload W_hh slice into registers ----
    ull wreg[WPT];
    {
        const ull* wp = (const ull*)W_hh + (size_t)rowG * (HDIM / 2) + w * WPT;
        #pragma unroll
        for (int i = 0; i < WPT; i++) wreg[i] = wp[i];
    }

    // ---- recurrence: ONE __syncthreads per step ----
    float c = 0.f;
    unsigned target = 0u;                  // = 128*t

    for (int t = 0; t < N; ++t) {
        float dot = 0.f;
        if (t > 0) {
            const int p = (t - 1) & 1;
            const unsigned tt = (unsigned)t;

            if (w == 0) {
                if (l < 4) {
                    // staggered pollers: lane l offsets its probe phase by
                    // ~130*l cycles; counter line sampled ~4x per L2 RT
                    unsigned t0 = clk32();
                    while (clk32() - t0 < (unsigned)(l * 130)) { }
                    for (;;) {
                        unsigned v = ld_acq_gpu(&g_cnt);
                        if ((int)(v - target) >= 0) {
                            asm volatile("st.release.cta.shared.u32 [%0], %1;"
                                         :: "r"(stepAddr), "r"(tt) : "memory");
                            break;
                        }
                        unsigned s;
                        asm volatile("ld.acquire.cta.shared.u32 %0, [%1];"
                                     : "=r"(s) : "r"(stepAddr) : "memory");
                        if ((int)(s - tt) >= 0) break;
                    }
                }
                __syncwarp();
            } else {
                // local smem spin: zero L2 traffic (unchanged from R7)
                unsigned v;
                do {
                    asm volatile("ld.acquire.cta.shared.u32 %0, [%1];"
                                 : "=r"(v) : "r"(stepAddr) : "memory");
                } while ((int)(v - tt) < 0);
            }

            // stage this warp's k-slice into its private smem region
            float4 hv = __ldcg((const float4*)(g_hbuf[p] + w * 128) + l);
            *((float4*)(sh_h + w * 128) + l) = hv;
            __syncwarp();

            const ull* hp = (const ull*)(sh_h + w * 128);
            ull c0 = 0, c1 = 0, c2 = 0, c3 = 0;
            #pragma unroll
            for (int i = 0; i < WPT; i += 4) {
                c0 = ffma2(wreg[i + 0], hp[i + 0], c0);
                c1 = ffma2(wreg[i + 1], hp[i + 1], c1);
                c2 = ffma2(wreg[i + 2], hp[i + 2], c2);
                c3 = ffma2(wreg[i + 3], hp[i + 3], c3);
            }
            c0 = fadd2(c0, c1); c2 = fadd2(c2, c3); c0 = fadd2(c0, c2);
            dot = pairsum(c0);
        }
        sh_part[t & 1][w * 32 + l] = dot;
        __syncthreads();

        if (w == 0) {
            float s = 0.f;
            #pragma unroll
            for (int ww = 0; ww < NWARP; ww++) s += sh_part[t & 1][ww * 32 + l];
            // activation on ALL 32 lanes (parallel MUFU), then gather
            float val = xg + s;
            float act = (gt == 2) ? tanhf(val) : sigf(val);
            float a_f = __shfl_sync(0xffffffffu, act, l + 8);
            float a_g = __shfl_sync(0xffffffffu, act, l + 16);
            float a_o = __shfl_sync(0xffffffffu, act, l + 24);
            float hn = 0.f;
            if (l < 8) {
                c  = a_f * c + act * a_g;       // act=i, a_f=f, a_g=g
                hn = a_o * tanhf(c);
                __stcg(&g_hbuf[t & 1][cta * 8 + l], hn);
            }
            __syncwarp();
            if (l == 0) {
                __threadfence();
                asm volatile("red.global.gpu.add.u32 [%0], %1;"
                             :: "l"(&g_cnt), "r"(1u) : "memory");
            }
            // out store AFTER release: fence never drains the DRAM write
            if (l < 8)
                __stcs(out + (size_t)t * HDIM + cta * 8 + l, hn);
        }
        target += NCTA;
        // no trailing barrier: sh_part for step t+1 has opposite parity; the
        // global counter requires ALL CTAs, bounding cross-CTA skew to 1 step.
    }
}

extern "C" void kernel_launch(void* const* d_in, const int* in_sizes, int n_in,
                              void* d_out, int out_size) {
    const float* x    = (const float*)d_in[0];
    const float* W_ih = (const float*)d_in[1];
    const float* W_hh = (const float*)d_in[2];
    const float* b_ih = (const float*)d_in[3];
    const float* b_hh = (const float*)d_in[4];
    float* out = (float*)d_out;
    const int N = out_size / HDIM;

    lstm_init_kernel<<<1, 32>>>();
    lstm_kernel<<<NCTA, TPB>>>(x, W_ih, W_hh, b_ih, b_hh, out, N);
}

// round 16
// speedup vs baseline: 1.1394x; 1.1394x over previous
#include <cuda_runtime.h>
#include <cstdint>

// ---------------------------------------------------------------------------
// Sequential LSTM rollout, N=10000 steps, H=1024.
// EXACT R7 kernel (best: 18.6ms) with ONE substitution:
//   producer tail  __threadfence(); red.global.gpu.add
//   ->             red.release.gpu.global.add          (single instruction)
// Release-on-the-RED orders the prior h st.cg stores before the counter
// increment (the ordering the fence provided) WITHOUT stalling the SM on a
// gpu-scope store drain — removing a serial stage from the grid pacer chain.
// Everything else byte-identical to R7:
//   Observe: lane0 of warp0 polls ld.acquire.gpu g_cnt >= 128*t, relays via
//   smem (st.release.cta / ld.acquire.cta spin). ONE __syncthreads per step.
//   Counter requires ALL CTAs -> 1-step skew bound -> parity-double-buffered
//   g_hbuf / sh_part overwrite-safe.
// CTA b owns h[8b..8b+8) and gate rows {g*1024 + 8b + j}.
// Warp w owns k in [128w,128w+128).
// ---------------------------------------------------------------------------

#define HDIM  1024
#define NCTA  128
#define TPB   256
#define NWARP 8
#define WPT   64           // f32x2 weight pairs per thread (=128 k floats)

typedef unsigned long long ull;

__device__ __align__(16) float g_hbuf[2][HDIM];
__device__ unsigned            g_cnt;

__device__ __forceinline__ ull ffma2(ull a, ull b, ull c) {
    ull d;
    asm("fma.rn.f32x2 %0, %1, %2, %3;" : "=l"(d) : "l"(a), "l"(b), "l"(c));
    return d;
}
__device__ __forceinline__ ull fadd2(ull a, ull b) {
    ull d;
    asm("add.rn.f32x2 %0, %1, %2;" : "=l"(d) : "l"(a), "l"(b));
    return d;
}
__device__ __forceinline__ float pairsum(ull a) {
    float lo = __uint_as_float((unsigned)(a & 0xffffffffull));
    float hi = __uint_as_float((unsigned)(a >> 32));
    return lo + hi;
}
__device__ __forceinline__ float sigf(float x) {
    return 1.0f / (1.0f + __expf(-x));
}
__device__ __forceinline__ unsigned ld_acq_gpu(const unsigned* p) {
    unsigned v;
    asm volatile("ld.acquire.gpu.u32 %0, [%1];" : "=r"(v) : "l"(p));
    return v;
}
__device__ __forceinline__ uint32_t smem_u32(const void* p) {
    uint32_t a;
    asm("{ .reg .u64 t; cvta.to.shared.u64 t, %1; cvt.u32.u64 %0, t; }"
        : "=r"(a) : "l"(p));
    return a;
}

__global__ void lstm_init_kernel() {
    if (threadIdx.x == 0) g_cnt = 0u;
}

__global__ void __launch_bounds__(TPB) lstm_kernel(
    const float* __restrict__ x,      // [1024]
    const float* __restrict__ W_ih,   // [4096,1024] row-major
    const float* __restrict__ W_hh,   // [4096,1024] row-major
    const float* __restrict__ b_ih,   // [4096]
    const float* __restrict__ b_hh,   // [4096]
    float* __restrict__ out,          // [N,1024]
    int N)
{
    __shared__ float    sh_h[HDIM];        // warp w owns [128w,128w+128): private
    __shared__ float    sh_part[2][TPB];   // parity-double-buffered partials
    __shared__ unsigned sh_step;           // monotonic step relay

    const int tid = threadIdx.x;
    const int w   = tid >> 5;
    const int l   = tid & 31;
    const int cta = blockIdx.x;
    const int gt  = l >> 3;                // gate 0..3 (i,f,g,o)
    const int jj  = l & 7;                 // local h index 0..7
    const int rowG = gt * HDIM + cta * 8 + jj;
    const uint32_t stepAddr = smem_u32(&sh_step);

    if (tid == 0) sh_step = 0u;

    // ---- stage x into shared (reuse sh_h) ----
    ((float4*)sh_h)[tid] = ((const float4*)x)[tid];
    __syncthreads();

    // ---- prologue: x_gates = x @ W_ih^T + b_ih + b_hh for this CTA's rows ----
    float xg = 0.f;
    {
        const ull* wp = (const ull*)W_ih + (size_t)rowG * (HDIM / 2) + w * WPT;
        const ull* hp = (const ull*)sh_h + w * WPT;
        ull a0 = 0, a1 = 0, a2 = 0, a3 = 0;
        #pragma unroll
        for (int i = 0; i < WPT; i += 4) {
            a0 = ffma2(wp[i + 0], hp[i + 0], a0);
            a1 = ffma2(wp[i + 1], hp[i + 1], a1);
            a2 = ffma2(wp[i + 2], hp[i + 2], a2);
            a3 = ffma2(wp[i + 3], hp[i + 3], a3);
        }
        a0 = fadd2(a0, a1); a2 = fadd2(a2, a3); a0 = fadd2(a0, a2);
        sh_part[0][w * 32 + l] = pairsum(a0);
        __syncthreads();
        if (w == 0) {
            float s = 0.f;
            #pragma unroll
            for (int ww = 0; ww < NWARP; ww++) s += sh_part[0][ww * 32 + l];
            xg = s + b_ih[rowG] + b_hh[rowG];
        }
        __syncthreads();
    }

    // ---- preload W_hh slice into registers ----
    ull wreg[WPT];
    {
        const ull* wp = (const ull*)W_hh + (size_t)rowG * (HDIM / 2) + w * WPT;
        #pragma unroll
        for (int i = 0; i < WPT; i++) wreg[i] = wp[i];
    }

    // ---- recurrence: ONE __syncthreads per step ----
    float c = 0.f;
    unsigned target = 0u;                  // = 128*t

    for (int t = 0; t < N; ++t) {
        float dot = 0.f;
        if (t > 0) {
            const int p = (t - 1) & 1;
            const unsigned tt = (unsigned)t;

            if (w == 0) {
                if (l == 0) {
                    // single poller per CTA on the aggregate counter
                    while ((int)(ld_acq_gpu(&g_cnt) - target) < 0) { }
                    asm volatile("st.release.cta.shared.u32 [%0], %1;"
                                 :: "r"(stepAddr), "r"(tt) : "memory");
                }
                __syncwarp();
            } else {
                // local smem spin: zero L2 traffic
                unsigned v;
                do {
                    asm volatile("ld.acquire.cta.shared.u32 %0, [%1];"
                                 : "=r"(v) : "r"(stepAddr) : "memory");
                } while ((int)(v - tt) < 0);
            }

            // stage this warp's k-slice into its private smem region
            float4 hv = __ldcg((const float4*)(g_hbuf[p] + w * 128) + l);
            *((float4*)(sh_h + w * 128) + l) = hv;
            __syncwarp();

            const ull* hp = (const ull*)(sh_h + w * 128);
            ull c0 = 0, c1 = 0, c2 = 0, c3 = 0;
            #pragma unroll
            for (int i = 0; i < WPT; i += 4) {
                c0 = ffma2(wreg[i + 0], hp[i + 0], c0);
                c1 = ffma2(wreg[i + 1], hp[i + 1], c1);
                c2 = ffma2(wreg[i + 2], hp[i + 2], c2);
                c3 = ffma2(wreg[i + 3], hp[i + 3], c3);
            }
            c0 = fadd2(c0, c1); c2 = fadd2(c2, c3); c0 = fadd2(c0, c2);
            dot = pairsum(c0);
        }
        sh_part[t & 1][w * 32 + l] = dot;
        __syncthreads();

        if (w == 0) {
            float s = 0.f;
            #pragma unroll
            for (int ww = 0; ww < NWARP; ww++) s += sh_part[t & 1][ww * 32 + l];
            // activation on ALL 32 lanes (parallel MUFU), then gather
            float val = xg + s;
            float act = (gt == 2) ? tanhf(val) : sigf(val);
            float a_f = __shfl_sync(0xffffffffu, act, l + 8);
            float a_g = __shfl_sync(0xffffffffu, act, l + 16);
            float a_o = __shfl_sync(0xffffffffu, act, l + 24);
            float hn = 0.f;
            if (l < 8) {
                c  = a_f * c + act * a_g;       // act=i, a_f=f, a_g=g
                hn = a_o * tanhf(c);
                __stcg(&g_hbuf[t & 1][cta * 8 + l], hn);
            }
            __syncwarp();
            if (l == 0) {
                // release-RED: orders the prior h stores before the increment
                // without an SM-stalling gpu-scope fence
                asm volatile("red.release.gpu.global.add.u32 [%0], %1;"
                             :: "l"(&g_cnt), "r"(1u) : "memory");
            }
            // out store AFTER release: never delays the publish
            if (l < 8)
                __stcs(out + (size_t)t * HDIM + cta * 8 + l, hn);
        }
        target += NCTA;
        // no trailing barrier: sh_part for step t+1 has opposite parity; the
        // global counter requires ALL CTAs, bounding cross-CTA skew to 1 step.
    }
}

extern "C" void kernel_launch(void* const* d_in, const int* in_sizes, int n_in,
                              void* d_out, int out_size) {
    const float* x    = (const float*)d_in[0];
    const float* W_ih = (const float*)d_in[1];
    const float* W_hh = (const float*)d_in[2];
    const float* b_ih = (const float*)d_in[3];
    const float* b_hh = (const float*)d_in[4];
    float* out = (float*)d_out;
    const int N = out_size / HDIM;

    lstm_init_kernel<<<1, 32>>>();
    lstm_kernel<<<NCTA, TPB>>>(x, W_ih, W_hh, b_ih, b_hh, out, N);
}